// round 3
// baseline (speedup 1.0000x reference)
#include <cuda_runtime.h>
#include <cuda_bf16.h>

// Problem constants: x[16,512,32,32], Q/K/V[512,512]
#define B_ 16
#define C_ 512
#define S_ 1024
#define BS_ (B_ * S_)   // 16384

// -------- scratch (device globals; no allocation allowed) --------
__device__ float g_xn[B_ * S_ * C_];     // normalized x, [B,S,C]
__device__ float g_q [B_ * S_ * C_];
__device__ float g_k [B_ * S_ * C_];
__device__ float g_v [B_ * S_ * C_];
__device__ float g_sc[B_ * S_ * S_];     // scores / attn weights, [B,S,S]
__device__ float g_mean[C_];
__device__ float g_rsig[C_];

// -------- packed f32x2 helpers (sm_100+ PTX) --------
__device__ __forceinline__ unsigned long long ffma2(unsigned long long a,
                                                    unsigned long long b,
                                                    unsigned long long c) {
    unsigned long long d;
    asm("fma.rn.f32x2 %0, %1, %2, %3;" : "=l"(d) : "l"(a), "l"(b), "l"(c));
    return d;
}
__device__ __forceinline__ unsigned long long pack2(float x) {
    unsigned long long d;
    asm("mov.b64 %0, {%1, %1};" : "=l"(d) : "f"(x));
    return d;
}
__device__ __forceinline__ float2 unpack2(unsigned long long v) {
    float2 r;
    asm("mov.b64 {%0, %1}, %2;" : "=f"(r.x), "=f"(r.y) : "l"(v));
    return r;
}

// -------- BatchNorm statistics: one block per channel --------
__global__ __launch_bounds__(256) void bn_stats_kernel(const float* __restrict__ x) {
    int c = blockIdx.x;
    int t = threadIdx.x;
    float s = 0.f, ss = 0.f;
    for (int b = 0; b < B_; ++b) {
        const float* p = x + ((size_t)b * C_ + c) * S_;
        for (int i = t; i < S_; i += 256) {
            float v = p[i];
            s += v;
            ss += v * v;
        }
    }
    #pragma unroll
    for (int o = 16; o > 0; o >>= 1) {
        s  += __shfl_down_sync(0xffffffffu, s,  o);
        ss += __shfl_down_sync(0xffffffffu, ss, o);
    }
    __shared__ float shs[8], shq[8];
    int w = t >> 5, l = t & 31;
    if (l == 0) { shs[w] = s; shq[w] = ss; }
    __syncthreads();
    if (t == 0) {
        float S = 0.f, Qq = 0.f;
        #pragma unroll
        for (int i = 0; i < 8; ++i) { S += shs[i]; Qq += shq[i]; }
        const float invN = 1.0f / (float)(B_ * S_);
        float mu  = S * invN;
        float var = Qq * invN - mu * mu;
        g_mean[c] = mu;
        g_rsig[c] = rsqrtf(var + 1e-5f);
    }
}

// -------- normalize + transpose [B,C,S] -> [B,S,C] --------
__global__ __launch_bounds__(256) void normalize_kernel(const float* __restrict__ x) {
    __shared__ float tile[32][33];
    int b  = blockIdx.z;
    int c0 = blockIdx.y * 32;
    int s0 = blockIdx.x * 32;
    int tx = threadIdx.x, ty = threadIdx.y;   // blockDim (32, 8)
    #pragma unroll
    for (int r = 0; r < 4; ++r) {
        int c = c0 + ty + 8 * r;
        tile[ty + 8 * r][tx] = x[((size_t)b * C_ + c) * S_ + s0 + tx];
    }
    __syncthreads();
    float mu = g_mean[c0 + tx];
    float rs = g_rsig[c0 + tx];
    #pragma unroll
    for (int r = 0; r < 4; ++r) {
        int s = s0 + ty + 8 * r;
        g_xn[((size_t)b * S_ + s) * C_ + c0 + tx] = (tile[tx][ty + 8 * r] - mu) * rs;
    }
}

// -------- fp32 GEMM (f32x2 packed FMA), 128x128x16 tile, 8x8/thread --------
// C[z] = alpha * A[z] * op(B[z])  (+ Res[z] if ADD_RES), op = transpose if TRANSB.
// A row-major [M,K]; B row-major [K,N] (NN) or [N,K] (NT). All dims % 128/16 == 0.
template <bool TRANSB, bool ADD_RES>
__global__ __launch_bounds__(256, 2) void gemm_kernel(
    const float* __restrict__ Ag, const float* __restrict__ Bg,
    float* __restrict__ Cg, const float* __restrict__ Res,
    int M, int N, int K,
    size_t sA, size_t sB, size_t sC, float alpha)
{
    __shared__ float As[16][132];   // stride 132 floats: 16B-aligned rows
    __shared__ float Bs[16][132];

    const int tid = threadIdx.x;
    const int tx  = tid & 15;          // n-tile coord
    const int ty  = tid >> 4;          // m-tile coord
    const int lr  = tid >> 2;          // transpose-load row (0..63)
    const int lc  = (tid & 3) * 4;     // transpose-load k offset
    const int bk  = tid >> 5;          // NN B-load k row (0..7)
    const int bn  = (tid & 31) * 4;    // NN B-load n offset

    const float* A = Ag + blockIdx.z * sA + (size_t)blockIdx.y * 128 * K;
    const float* Bp;
    if (TRANSB) Bp = Bg + blockIdx.z * sB + (size_t)blockIdx.x * 128 * K;
    else        Bp = Bg + blockIdx.z * sB + (size_t)blockIdx.x * 128;
    float*       Cp = Cg + blockIdx.z * sC + (size_t)blockIdx.y * 128 * N + (size_t)blockIdx.x * 128;
    const float* Rp = ADD_RES
        ? (Res + blockIdx.z * sC + (size_t)blockIdx.y * 128 * N + (size_t)blockIdx.x * 128)
        : nullptr;

    unsigned long long acc[8][4];
    #pragma unroll
    for (int i = 0; i < 8; ++i)
        #pragma unroll
        for (int j = 0; j < 4; ++j) acc[i][j] = 0ull;

    for (int k0 = 0; k0 < K; k0 += 16) {
        // ---- A tile load (transpose into As[k][m]) ----
        float4 a0 = *(const float4*)(A + (size_t)lr * K + k0 + lc);
        float4 a1 = *(const float4*)(A + (size_t)(lr + 64) * K + k0 + lc);
        As[lc + 0][lr]      = a0.x; As[lc + 1][lr]      = a0.y;
        As[lc + 2][lr]      = a0.z; As[lc + 3][lr]      = a0.w;
        As[lc + 0][lr + 64] = a1.x; As[lc + 1][lr + 64] = a1.y;
        As[lc + 2][lr + 64] = a1.z; As[lc + 3][lr + 64] = a1.w;
        // ---- B tile load ----
        if (TRANSB) {
            float4 b0 = *(const float4*)(Bp + (size_t)lr * K + k0 + lc);
            float4 b1 = *(const float4*)(Bp + (size_t)(lr + 64) * K + k0 + lc);
            Bs[lc + 0][lr]      = b0.x; Bs[lc + 1][lr]      = b0.y;
            Bs[lc + 2][lr]      = b0.z; Bs[lc + 3][lr]      = b0.w;
            Bs[lc + 0][lr + 64] = b1.x; Bs[lc + 1][lr + 64] = b1.y;
            Bs[lc + 2][lr + 64] = b1.z; Bs[lc + 3][lr + 64] = b1.w;
        } else {
            float4 b0 = *(const float4*)(Bp + (size_t)(k0 + bk) * N + bn);
            float4 b1 = *(const float4*)(Bp + (size_t)(k0 + bk + 8) * N + bn);
            *(float4*)&Bs[bk][bn]     = b0;
            *(float4*)&Bs[bk + 8][bn] = b1;
        }
        __syncthreads();

        #pragma unroll
        for (int kk = 0; kk < 16; ++kk) {
            float4 av0 = *(const float4*)&As[kk][ty * 4];
            float4 av1 = *(const float4*)&As[kk][64 + ty * 4];
            ulonglong2 bb0 = *(const ulonglong2*)&Bs[kk][tx * 4];
            ulonglong2 bb1 = *(const ulonglong2*)&Bs[kk][64 + tx * 4];
            unsigned long long bB[4] = { bb0.x, bb0.y, bb1.x, bb1.y };
            float am[8] = { av0.x, av0.y, av0.z, av0.w,
                            av1.x, av1.y, av1.z, av1.w };
            #pragma unroll
            for (int i = 0; i < 8; ++i) {
                unsigned long long ap = pack2(am[i]);
                #pragma unroll
                for (int j = 0; j < 4; ++j)
                    acc[i][j] = ffma2(ap, bB[j], acc[i][j]);
            }
        }
        __syncthreads();
    }

    // ---- epilogue ----
    #pragma unroll
    for (int i = 0; i < 8; ++i) {
        int row = (i < 4) ? (ty * 4 + i) : (64 + ty * 4 + (i - 4));
        float2 p0 = unpack2(acc[i][0]);
        float2 p1 = unpack2(acc[i][1]);
        float2 p2 = unpack2(acc[i][2]);
        float2 p3 = unpack2(acc[i][3]);
        float4 lo = make_float4(p0.x * alpha, p0.y * alpha, p1.x * alpha, p1.y * alpha);
        float4 hi = make_float4(p2.x * alpha, p2.y * alpha, p3.x * alpha, p3.y * alpha);
        size_t base = (size_t)row * N;
        if (ADD_RES) {
            float4 r0 = *(const float4*)(Rp + base + tx * 4);
            float4 r1 = *(const float4*)(Rp + base + 64 + tx * 4);
            lo.x += r0.x; lo.y += r0.y; lo.z += r0.z; lo.w += r0.w;
            hi.x += r1.x; hi.y += r1.y; hi.z += r1.z; hi.w += r1.w;
        }
        *(float4*)(Cp + base + tx * 4)      = lo;
        *(float4*)(Cp + base + 64 + tx * 4) = hi;
    }
}

// -------- softmax over the BATCH axis: one thread per (q,k) pair --------
__global__ __launch_bounds__(256) void softmax_batch_kernel() {
    int idx = blockIdx.x * 256 + threadIdx.x;     // < S_*S_
    float v[B_];
    float m = -3.4e38f;
    #pragma unroll
    for (int b = 0; b < B_; ++b) {
        v[b] = g_sc[(size_t)b * (S_ * S_) + idx];
        m = fmaxf(m, v[b]);
    }
    float s = 0.f;
    #pragma unroll
    for (int b = 0; b < B_; ++b) {
        v[b] = expf(v[b] - m);
        s += v[b];
    }
    float inv = 1.0f / s;
    #pragma unroll
    for (int b = 0; b < B_; ++b)
        g_sc[(size_t)b * (S_ * S_) + idx] = v[b] * inv;
}

extern "C" void kernel_launch(void* const* d_in, const int* in_sizes, int n_in,
                              void* d_out, int out_size) {
    const float* x = (const float*)d_in[0];
    const float* Q = (const float*)d_in[1];
    const float* K = (const float*)d_in[2];
    const float* V = (const float*)d_in[3];
    float* out = (float*)d_out;

    float *xn, *q, *k, *v, *sc;
    cudaGetSymbolAddress((void**)&xn, g_xn);
    cudaGetSymbolAddress((void**)&q,  g_q);
    cudaGetSymbolAddress((void**)&k,  g_k);
    cudaGetSymbolAddress((void**)&v,  g_v);
    cudaGetSymbolAddress((void**)&sc, g_sc);

    // 1) BatchNorm stats (per channel over B*S)
    bn_stats_kernel<<<C_, 256>>>(x);

    // 2) normalize + transpose -> xn [B,S,C]
    normalize_kernel<<<dim3(S_ / 32, C_ / 32, B_), dim3(32, 8)>>>(x);

    // 3) q/k/v = xn @ {Q,K,V}   [16384,512] x [512,512]
    dim3 g1(C_ / 128, BS_ / 128, 1);
    gemm_kernel<false, false><<<g1, 256>>>(xn, Q, q, nullptr, BS_, C_, C_, 0, 0, 0, 1.0f);
    gemm_kernel<false, false><<<g1, 256>>>(xn, K, k, nullptr, BS_, C_, C_, 0, 0, 0, 1.0f);
    gemm_kernel<false, false><<<g1, 256>>>(xn, V, v, nullptr, BS_, C_, C_, 0, 0, 0, 1.0f);

    // 4) scores[b] = (q[b] @ k[b]^T) / sqrt(C)   (NT, batched)
    dim3 g2(S_ / 128, S_ / 128, B_);
    gemm_kernel<true, false><<<g2, 256>>>(q, k, sc, nullptr, S_, S_, C_,
                                          (size_t)S_ * C_, (size_t)S_ * C_,
                                          (size_t)S_ * S_, 0.04419417382415922f);

    // 5) softmax over batch axis (Softmax2d quirk)
    softmax_batch_kernel<<<(S_ * S_) / 256, 256>>>();

    // 6) out[b] = attn_w[b] @ v[b] + xn[b]   (NN, batched, fused residual)
    dim3 g3(C_ / 128, S_ / 128, B_);
    gemm_kernel<false, true><<<g3, 256>>>(sc, v, out, xn, S_, C_, S_,
                                          (size_t)S_ * S_, (size_t)S_ * C_,
                                          (size_t)S_ * C_, 1.0f);
}

// round 5
// speedup vs baseline: 1.0611x; 1.0611x over previous
#include <cuda_runtime.h>
#include <cuda_bf16.h>

// Problem constants: x[16,512,32,32], Q/K/V[512,512]
#define B_ 16
#define C_ 512
#define S_ 1024
#define BS_ (B_ * S_)   // 16384

// -------- scratch (device globals; no allocation allowed) --------
__device__ float g_xn[B_ * S_ * C_];     // normalized x, [B,S,C]
__device__ float g_q [B_ * S_ * C_];
__device__ float g_k [B_ * S_ * C_];
__device__ float g_v [B_ * S_ * C_];
__device__ float g_sc[B_ * S_ * S_];     // scores / attn weights, [B,S,S]
__device__ float g_mean[C_];
__device__ float g_rsig[C_];

// -------- packed f32x2 helpers (sm_100+ PTX) --------
__device__ __forceinline__ unsigned long long ffma2(unsigned long long a,
                                                    unsigned long long b,
                                                    unsigned long long c) {
    unsigned long long d;
    asm("fma.rn.f32x2 %0, %1, %2, %3;" : "=l"(d) : "l"(a), "l"(b), "l"(c));
    return d;
}
__device__ __forceinline__ unsigned long long pack2(float x) {
    unsigned long long d;
    asm("mov.b64 %0, {%1, %1};" : "=l"(d) : "f"(x));
    return d;
}
__device__ __forceinline__ float2 unpack2(unsigned long long v) {
    float2 r;
    asm("mov.b64 {%0, %1}, %2;" : "=f"(r.x), "=f"(r.y) : "l"(v));
    return r;
}

// -------- BatchNorm statistics: one block per channel --------
__global__ __launch_bounds__(256) void bn_stats_kernel(const float* __restrict__ x) {
    int c = blockIdx.x;
    int t = threadIdx.x;
    float s = 0.f, ss = 0.f;
    for (int b = 0; b < B_; ++b) {
        const float* p = x + ((size_t)b * C_ + c) * S_;
        for (int i = t; i < S_; i += 256) {
            float v = p[i];
            s += v;
            ss += v * v;
        }
    }
    #pragma unroll
    for (int o = 16; o > 0; o >>= 1) {
        s  += __shfl_down_sync(0xffffffffu, s,  o);
        ss += __shfl_down_sync(0xffffffffu, ss, o);
    }
    __shared__ float shs[8], shq[8];
    int w = t >> 5, l = t & 31;
    if (l == 0) { shs[w] = s; shq[w] = ss; }
    __syncthreads();
    if (t == 0) {
        float S = 0.f, Qq = 0.f;
        #pragma unroll
        for (int i = 0; i < 8; ++i) { S += shs[i]; Qq += shq[i]; }
        const float invN = 1.0f / (float)(B_ * S_);
        float mu  = S * invN;
        float var = Qq * invN - mu * mu;
        g_mean[c] = mu;
        g_rsig[c] = rsqrtf(var + 1e-5f);
    }
}

// -------- normalize + transpose [B,C,S] -> [B,S,C] --------
__global__ __launch_bounds__(256) void normalize_kernel(const float* __restrict__ x) {
    __shared__ float tile[32][33];
    int b  = blockIdx.z;
    int c0 = blockIdx.y * 32;
    int s0 = blockIdx.x * 32;
    int tx = threadIdx.x, ty = threadIdx.y;   // blockDim (32, 8)
    #pragma unroll
    for (int r = 0; r < 4; ++r) {
        int c = c0 + ty + 8 * r;
        tile[ty + 8 * r][tx] = x[((size_t)b * C_ + c) * S_ + s0 + tx];
    }
    __syncthreads();
    float mu = g_mean[c0 + tx];
    float rs = g_rsig[c0 + tx];
    #pragma unroll
    for (int r = 0; r < 4; ++r) {
        int s = s0 + ty + 8 * r;
        g_xn[((size_t)b * S_ + s) * C_ + c0 + tx] = (tile[tx][ty + 8 * r] - mu) * rs;
    }
}

// -------- fp32 GEMM (f32x2 packed FMA), 128x128x16 tile, 8x8/thread --------
// Double-buffered smem, LDG prefetch into registers, ONE sync per k-iter.
// C[z] = alpha * A[z] * op(B[z])  (+ Res[z] if ADD_RES), op = transpose if TRANSB.
template <bool TRANSB, bool ADD_RES>
__global__ __launch_bounds__(256, 2) void gemm_kernel(
    const float* __restrict__ Ag, const float* __restrict__ Bg,
    float* __restrict__ Cg, const float* __restrict__ Res,
    int M, int N, int K,
    size_t sA, size_t sB, size_t sC, float alpha)
{
    __shared__ float As[2][16][132];
    __shared__ float Bs[2][16][132];

    const int tid = threadIdx.x;
    const int tx  = tid & 15;          // n-tile coord
    const int ty  = tid >> 4;          // m-tile coord
    const int lr  = tid >> 2;          // transpose-load row (0..63)
    const int lc  = (tid & 3) * 4;     // transpose-load k offset
    const int bk  = tid >> 5;          // NN B-load k row (0..7)
    const int bn  = (tid & 31) * 4;    // NN B-load n offset

    const float* A = Ag + blockIdx.z * sA + (size_t)blockIdx.y * 128 * K;
    const float* Bp;
    if (TRANSB) Bp = Bg + blockIdx.z * sB + (size_t)blockIdx.x * 128 * K;
    else        Bp = Bg + blockIdx.z * sB + (size_t)blockIdx.x * 128;
    float*       Cp = Cg + blockIdx.z * sC + (size_t)blockIdx.y * 128 * N + (size_t)blockIdx.x * 128;
    const float* Rp = ADD_RES
        ? (Res + blockIdx.z * sC + (size_t)blockIdx.y * 128 * N + (size_t)blockIdx.x * 128)
        : nullptr;

    unsigned long long acc[8][4];
    #pragma unroll
    for (int i = 0; i < 8; ++i)
        #pragma unroll
        for (int j = 0; j < 4; ++j) acc[i][j] = 0ull;

    float4 a0, a1, b0, b1;   // in-flight tile (registers)

    auto LOAD = [&](int k0) {
        a0 = *(const float4*)(A + (size_t)lr * K + k0 + lc);
        a1 = *(const float4*)(A + (size_t)(lr + 64) * K + k0 + lc);
        if (TRANSB) {
            b0 = *(const float4*)(Bp + (size_t)lr * K + k0 + lc);
            b1 = *(const float4*)(Bp + (size_t)(lr + 64) * K + k0 + lc);
        } else {
            b0 = *(const float4*)(Bp + (size_t)(k0 + bk) * N + bn);
            b1 = *(const float4*)(Bp + (size_t)(k0 + bk + 8) * N + bn);
        }
    };
    auto STORE = [&](int buf) {
        As[buf][lc + 0][lr]      = a0.x; As[buf][lc + 1][lr]      = a0.y;
        As[buf][lc + 2][lr]      = a0.z; As[buf][lc + 3][lr]      = a0.w;
        As[buf][lc + 0][lr + 64] = a1.x; As[buf][lc + 1][lr + 64] = a1.y;
        As[buf][lc + 2][lr + 64] = a1.z; As[buf][lc + 3][lr + 64] = a1.w;
        if (TRANSB) {
            Bs[buf][lc + 0][lr]      = b0.x; Bs[buf][lc + 1][lr]      = b0.y;
            Bs[buf][lc + 2][lr]      = b0.z; Bs[buf][lc + 3][lr]      = b0.w;
            Bs[buf][lc + 0][lr + 64] = b1.x; Bs[buf][lc + 1][lr + 64] = b1.y;
            Bs[buf][lc + 2][lr + 64] = b1.z; Bs[buf][lc + 3][lr + 64] = b1.w;
        } else {
            *(float4*)&Bs[buf][bk][bn]     = b0;
            *(float4*)&Bs[buf][bk + 8][bn] = b1;
        }
    };
    auto COMPUTE = [&](int buf) {
        #pragma unroll
        for (int kk = 0; kk < 16; ++kk) {
            float4 av0 = *(const float4*)&As[buf][kk][ty * 4];
            float4 av1 = *(const float4*)&As[buf][kk][64 + ty * 4];
            ulonglong2 bb0 = *(const ulonglong2*)&Bs[buf][kk][tx * 4];
            ulonglong2 bb1 = *(const ulonglong2*)&Bs[buf][kk][64 + tx * 4];
            unsigned long long bB[4] = { bb0.x, bb0.y, bb1.x, bb1.y };
            float am[8] = { av0.x, av0.y, av0.z, av0.w,
                            av1.x, av1.y, av1.z, av1.w };
            #pragma unroll
            for (int i = 0; i < 8; ++i) {
                unsigned long long ap = pack2(am[i]);
                #pragma unroll
                for (int j = 0; j < 4; ++j)
                    acc[i][j] = ffma2(ap, bB[j], acc[i][j]);
            }
        }
    };

    // ---- pipelined mainloop: one __syncthreads per k-iteration ----
    LOAD(0);
    STORE(0);
    __syncthreads();
    int buf = 0;
    for (int k0 = 16; k0 < K; k0 += 16) {
        LOAD(k0);          // prefetch next tile (latency hidden by COMPUTE)
        COMPUTE(buf);
        STORE(buf ^ 1);
        __syncthreads();
        buf ^= 1;
    }
    COMPUTE(buf);

    // ---- epilogue ----
    #pragma unroll
    for (int i = 0; i < 8; ++i) {
        int row = (i < 4) ? (ty * 4 + i) : (64 + ty * 4 + (i - 4));
        float2 p0 = unpack2(acc[i][0]);
        float2 p1 = unpack2(acc[i][1]);
        float2 p2 = unpack2(acc[i][2]);
        float2 p3 = unpack2(acc[i][3]);
        float4 lo = make_float4(p0.x * alpha, p0.y * alpha, p1.x * alpha, p1.y * alpha);
        float4 hi = make_float4(p2.x * alpha, p2.y * alpha, p3.x * alpha, p3.y * alpha);
        size_t base = (size_t)row * N;
        if (ADD_RES) {
            float4 r0 = *(const float4*)(Rp + base + tx * 4);
            float4 r1 = *(const float4*)(Rp + base + 64 + tx * 4);
            lo.x += r0.x; lo.y += r0.y; lo.z += r0.z; lo.w += r0.w;
            hi.x += r1.x; hi.y += r1.y; hi.z += r1.z; hi.w += r1.w;
        }
        *(float4*)(Cp + base + tx * 4)      = lo;
        *(float4*)(Cp + base + 64 + tx * 4) = hi;
    }
}

// -------- softmax over the BATCH axis: one thread per (q,k) pair --------
__global__ __launch_bounds__(256) void softmax_batch_kernel() {
    int idx = blockIdx.x * 256 + threadIdx.x;     // < S_*S_
    float v[B_];
    float m = -3.4e38f;
    #pragma unroll
    for (int b = 0; b < B_; ++b) {
        v[b] = g_sc[(size_t)b * (S_ * S_) + idx];
        m = fmaxf(m, v[b]);
    }
    float s = 0.f;
    #pragma unroll
    for (int b = 0; b < B_; ++b) {
        v[b] = expf(v[b] - m);
        s += v[b];
    }
    float inv = 1.0f / s;
    #pragma unroll
    for (int b = 0; b < B_; ++b)
        g_sc[(size_t)b * (S_ * S_) + idx] = v[b] * inv;
}

extern "C" void kernel_launch(void* const* d_in, const int* in_sizes, int n_in,
                              void* d_out, int out_size) {
    const float* x = (const float*)d_in[0];
    const float* Q = (const float*)d_in[1];
    const float* K = (const float*)d_in[2];
    const float* V = (const float*)d_in[3];
    float* out = (float*)d_out;

    float *xn, *q, *k, *v, *sc;
    cudaGetSymbolAddress((void**)&xn, g_xn);
    cudaGetSymbolAddress((void**)&q,  g_q);
    cudaGetSymbolAddress((void**)&k,  g_k);
    cudaGetSymbolAddress((void**)&v,  g_v);
    cudaGetSymbolAddress((void**)&sc, g_sc);

    // 1) BatchNorm stats (per channel over B*S)
    bn_stats_kernel<<<C_, 256>>>(x);

    // 2) normalize + transpose -> xn [B,S,C]
    normalize_kernel<<<dim3(S_ / 32, C_ / 32, B_), dim3(32, 8)>>>(x);

    // 3) q/k/v = xn @ {Q,K,V}   [16384,512] x [512,512]
    dim3 g1(C_ / 128, BS_ / 128, 1);
    gemm_kernel<false, false><<<g1, 256>>>(xn, Q, q, nullptr, BS_, C_, C_, 0, 0, 0, 1.0f);
    gemm_kernel<false, false><<<g1, 256>>>(xn, K, k, nullptr, BS_, C_, C_, 0, 0, 0, 1.0f);
    gemm_kernel<false, false><<<g1, 256>>>(xn, V, v, nullptr, BS_, C_, C_, 0, 0, 0, 1.0f);

    // 4) scores[b] = (q[b] @ k[b]^T) / sqrt(C)   (NT, batched)
    dim3 g2(S_ / 128, S_ / 128, B_);
    gemm_kernel<true, false><<<g2, 256>>>(q, k, sc, nullptr, S_, S_, C_,
                                          (size_t)S_ * C_, (size_t)S_ * C_,
                                          (size_t)S_ * S_, 0.04419417382415922f);

    // 5) softmax over batch axis (Softmax2d quirk)
    softmax_batch_kernel<<<(S_ * S_) / 256, 256>>>();

    // 6) out[b] = attn_w[b] @ v[b] + xn[b]   (NN, batched, fused residual)
    dim3 g3(C_ / 128, S_ / 128, B_);
    gemm_kernel<false, true><<<g3, 256>>>(sc, v, out, xn, S_, C_, S_,
                                          (size_t)S_ * S_, (size_t)S_ * C_,
                                          (size_t)S_ * C_, 1.0f);
}